// round 12
// baseline (speedup 1.0000x reference)
#include <cuda_runtime.h>
#include <cuda_bf16.h>
#include <math.h>

#define Bc   16
#define Mc   256
#define Nc   512
#define H1c  16
#define H2c  8
#define Uc   8
#define OUTc 4
#define BNc  (Bc*Nc)

typedef unsigned long long ull;

// ---- packed f32x2 helpers (sm_100+) ----
__device__ __forceinline__ ull pk2(float lo, float hi) {
    ull r; asm("mov.b64 %0, {%1, %2};" : "=l"(r) : "f"(lo), "f"(hi)); return r;
}
__device__ __forceinline__ float2 upk2(ull v) {
    float2 r; asm("mov.b64 {%0, %1}, %2;" : "=f"(r.x), "=f"(r.y) : "l"(v)); return r;
}
__device__ __forceinline__ ull ffma2(ull a, ull b, ull c) {
    ull d; asm("fma.rn.f32x2 %0, %1, %2, %3;" : "=l"(d) : "l"(a), "l"(b), "l"(c)); return d;
}

__device__ __forceinline__ float sigmoidf_fast(float x) {
    return __fdividef(1.f, 1.f + __expf(-x));
}
__device__ __forceinline__ float tanhf_fast(float x) {
    float e = __expf(2.f * x);
    return 1.f - __fdividef(2.f, e + 1.f);
}

// ---- scratch (static device globals; no allocation) ----
__device__ float g_G[(size_t)Bc*Nc*Nc];     // 16 MB Gram
__device__ float g_g[BNc*H1c];              // GRU hidden
__device__ float g_ab[2][BNc*H1c];          // a_i per layer buffer
__device__ float g_cb[2][BNc*H1c];          // c_j per layer buffer
__device__ __nv_bfloat16 g_AThi[(size_t)Bc*Nc*Mc];  // A^T split-bf16 hi (4MB)
__device__ __nv_bfloat16 g_ATlo[(size_t)Bc*Nc*Mc];  // A^T split-bf16 lo (4MB)

// ---- m16n8k16 bf16 mma (row.col, f32 accum) ----
__device__ __forceinline__ void mma_bf16(float d[4], const unsigned a[4],
                                         const unsigned b0, const unsigned b1) {
    asm volatile(
        "mma.sync.aligned.m16n8k16.row.col.f32.bf16.bf16.f32 "
        "{%0,%1,%2,%3}, {%4,%5,%6,%7}, {%8,%9}, {%0,%1,%2,%3};"
        : "+f"(d[0]), "+f"(d[1]), "+f"(d[2]), "+f"(d[3])
        : "r"(a[0]), "r"(a[1]), "r"(a[2]), "r"(a[3]), "r"(b0), "r"(b1));
}

__device__ __forceinline__ void ldsm4(unsigned r[4], const void* p) {
    unsigned addr = (unsigned)__cvta_generic_to_shared(p);
    asm volatile("ldmatrix.sync.aligned.m8n8.x4.shared.b16 {%0,%1,%2,%3}, [%4];"
                 : "=r"(r[0]), "=r"(r[1]), "=r"(r[2]), "=r"(r[3]) : "r"(addr));
}

// ============================================================
// K0: transpose + split A (f32 [B,M,N]) -> AT hi/lo (bf16 [B,N,M]).
// ============================================================
__global__ void __launch_bounds__(256) convert_kernel(const float* __restrict__ A) {
    int b = blockIdx.z;
    int n0 = blockIdx.x * 32, m0 = blockIdx.y * 32;
    int tx = threadIdx.x, ty = threadIdx.y;   // (32, 8)
    __shared__ float s[32][33];

    const float* Ab = A + (size_t)b * Mc * Nc;
#pragma unroll
    for (int q = 0; q < 4; q++) {
        int r = ty + q * 8;
        s[r][tx] = Ab[(size_t)(m0 + r) * Nc + n0 + tx];
    }
    __syncthreads();
    size_t base = (size_t)b * Nc * Mc;
#pragma unroll
    for (int q = 0; q < 4; q++) {
        int nl = ty + q * 8;
        float v = s[tx][nl];              // = A[m0+tx][n0+nl]
        __nv_bfloat16 hi = __float2bfloat16_rn(v);
        float hif = __bfloat162float(hi);
        __nv_bfloat16 lo = __float2bfloat16_rn(v - hif);
        size_t o = base + (size_t)(n0 + nl) * Mc + m0 + tx;
        g_AThi[o] = hi;
        g_ATlo[o] = lo;
    }
}

// ============================================================
// K1: G = A^T A via split-bf16 mma (3 terms), symmetric tiles.
// (R11 proven: k-chunk 64 + reg prefetch + ldmatrix; unchanged)
// ============================================================
__global__ void __launch_bounds__(256) gram_mma(void) {
    int b = blockIdx.y;
    int idx = blockIdx.x;                 // 0..35 -> (ti<=tj)
    int ti = 0;
    while (idx >= 8 - ti) { idx -= 8 - ti; ti++; }
    int tj = ti + idx;
    int i0 = ti * 64, j0 = tj * 64;

    int tid = threadIdx.x;
    int w = tid >> 5, lane = tid & 31;
    int g = lane >> 2, t2 = (lane & 3) * 2;
    int wr = w >> 2, wc = w & 3;          // warp tile: i = wr*32.., j = wc*16..

    __shared__ __align__(16) unsigned char sraw[4 * 64 * 72 * 2];
    unsigned short (*TIh)[72] = (unsigned short(*)[72])(sraw);
    unsigned short (*TIl)[72] = (unsigned short(*)[72])(sraw + 9216);
    unsigned short (*TJh)[72] = (unsigned short(*)[72])(sraw + 18432);
    unsigned short (*TJl)[72] = (unsigned short(*)[72])(sraw + 27648);
    float (*Ds)[67] = (float(*)[67])(sraw);   // overlay AFTER compute

    const unsigned short* ATh = (const unsigned short*)g_AThi + (size_t)b * Nc * Mc;
    const unsigned short* ATl = (const unsigned short*)g_ATlo + (size_t)b * Nc * Mc;

    float D[2][2][4];
#pragma unroll
    for (int mi = 0; mi < 2; mi++)
#pragma unroll
        for (int nj = 0; nj < 2; nj++)
#pragma unroll
            for (int q = 0; q < 4; q++) D[mi][nj][q] = 0.f;

    int tilesel = tid >> 6;
    int r2 = tid & 63;
    int hh = r2 & 7;
    int rb = r2 >> 3;
    const unsigned short* srcb = ((tilesel & 1) == 0) ? ATh : ATl;
    int rbase = (tilesel < 2) ? i0 : j0;
    unsigned short (*dstt)[72] =
        (tilesel == 0) ? TIh : (tilesel == 1) ? TIl : (tilesel == 2) ? TJh : TJl;

    int lrow = (lane & 7) + ((lane >> 3) & 1) * 8;
    int lcol = (lane >> 4) * 8;

    uint4 buf[8];
#pragma unroll
    for (int q = 0; q < 8; q++)
        buf[q] = *(const uint4*)&srcb[(size_t)(rbase + rb + q * 8) * Mc + hh * 8];

    for (int c = 0; c < 4; c++) {
        __syncthreads();
#pragma unroll
        for (int q = 0; q < 8; q++)
            *(uint4*)&dstt[rb + q * 8][hh * 8] = buf[q];
        __syncthreads();
        if (c < 3) {
            int cnext = (c + 1) * 64;
#pragma unroll
            for (int q = 0; q < 8; q++)
                buf[q] = *(const uint4*)&srcb[(size_t)(rbase + rb + q * 8) * Mc
                                              + cnext + hh * 8];
        }
#pragma unroll
        for (int kk = 0; kk < 4; kk++) {
            int kc = kk * 16 + lcol;
            unsigned Ah[2][4], Al[2][4], Bh[4], Bl[4];
#pragma unroll
            for (int mi = 0; mi < 2; mi++) {
                ldsm4(Ah[mi], &TIh[wr * 32 + mi * 16 + lrow][kc]);
                ldsm4(Al[mi], &TIl[wr * 32 + mi * 16 + lrow][kc]);
            }
            ldsm4(Bh, &TJh[wc * 16 + lrow][kc]);
            ldsm4(Bl, &TJl[wc * 16 + lrow][kc]);
#pragma unroll
            for (int mi = 0; mi < 2; mi++) {
                mma_bf16(D[mi][0], Ah[mi], Bh[0], Bh[2]);
                mma_bf16(D[mi][0], Ah[mi], Bl[0], Bl[2]);
                mma_bf16(D[mi][0], Al[mi], Bh[0], Bh[2]);
                mma_bf16(D[mi][1], Ah[mi], Bh[1], Bh[3]);
                mma_bf16(D[mi][1], Ah[mi], Bl[1], Bl[3]);
                mma_bf16(D[mi][1], Al[mi], Bh[1], Bh[3]);
            }
        }
    }

    __syncthreads();
#pragma unroll
    for (int mi = 0; mi < 2; mi++)
#pragma unroll
        for (int nj = 0; nj < 2; nj++) {
            int rr = wr * 32 + mi * 16 + g;
            int cc = wc * 16 + nj * 8 + t2;
            Ds[rr][cc]     = D[mi][nj][0];
            Ds[rr][cc + 1] = D[mi][nj][1];
            Ds[rr + 8][cc]     = D[mi][nj][2];
            Ds[rr + 8][cc + 1] = D[mi][nj][3];
        }
    __syncthreads();

    float* Gb = g_G + (size_t)b * Nc * Nc;
    int r = tid >> 2, c0 = (tid & 3) * 16;
#pragma unroll
    for (int q = 0; q < 4; q++) {
        float4 v = make_float4(Ds[r][c0 + q * 4], Ds[r][c0 + q * 4 + 1],
                               Ds[r][c0 + q * 4 + 2], Ds[r][c0 + q * 4 + 3]);
        *(float4*)(Gb + (size_t)(i0 + r) * Nc + j0 + c0 + q * 4) = v;
    }
    if (ti != tj) {
#pragma unroll
        for (int q = 0; q < 4; q++) {
            float4 v = make_float4(Ds[c0 + q * 4][r], Ds[c0 + q * 4 + 1][r],
                                   Ds[c0 + q * 4 + 2][r], Ds[c0 + q * 4 + 3][r]);
            *(float4*)(Gb + (size_t)(j0 + r) * Nc + i0 + c0 + q * 4) = v;
        }
    }
}

// ============================================================
// K2: ATy, diag(G), u0; zero g; a,c -> buffer 0. (unchanged)
// ============================================================
__global__ void init_kernel(const float* __restrict__ A, const float* __restrict__ y,
                            const float* __restrict__ sigma2,
                            const float* __restrict__ w_init, const float* __restrict__ b_init,
                            const float* __restrict__ w_p1, const float* __restrict__ b_p1) {
    int b = blockIdx.y;
    int n = blockIdx.x * 128 + threadIdx.x;
    __shared__ float sy[Mc];
    for (int m = threadIdx.x; m < Mc; m += 128) sy[m] = y[b * Mc + m];
    __syncthreads();

    const float* Ab = A + (size_t)b * Mc * Nc + n;
    float aty = 0.f;
#pragma unroll 8
    for (int m = 0; m < Mc; m++) aty = fmaf(Ab[(size_t)m * Nc], sy[m], aty);

    float diag = g_G[(size_t)b * Nc * Nc + (size_t)n * Nc + n];
    float sig = sigma2[b];
    int node = b * Nc + n;

    float u[Uc];
#pragma unroll
    for (int o = 0; o < Uc; o++) {
        u[o] = b_init[o] + w_init[o * 3 + 0] * aty + w_init[o * 3 + 1] * diag
             + w_init[o * 3 + 2] * sig;
    }
#pragma unroll
    for (int k = 0; k < H1c; k++) g_g[node * H1c + k] = 0.f;

#pragma unroll
    for (int o = 0; o < H1c; o++) {
        float av = b_p1[o] + w_p1[o * 18 + 17] * sig;
        float cv = 0.f;
#pragma unroll
        for (int k = 0; k < Uc; k++) {
            av = fmaf(w_p1[o * 18 + k], u[k], av);
            cv = fmaf(w_p1[o * 18 + 8 + k], u[k], cv);
        }
        g_ab[0][node * H1c + o] = av;
        g_cb[0][node * H1c + o] = cv;
    }
}

// ============================================================
// K3: fused pair + GRU (+ readout on last layer).
// R9 split-K layout; GEMV now f32x2-packed (fma-pipe-bound ->
// halving GEMV FFMA issue converts directly to time).
// ============================================================
__global__ void __launch_bounds__(256, 2)
pair_fused(const float* __restrict__ w_p1, const float* __restrict__ b_p1,
           const float* __restrict__ w_p2, const float* __restrict__ b_p2,
           const float* __restrict__ w_p3, const float* __restrict__ b_p3,
           const float* __restrict__ w_ih, const float* __restrict__ b_ih,
           const float* __restrict__ w_hh, const float* __restrict__ b_hh,
           const float* __restrict__ w_up, const float* __restrict__ b_up,
           const float* __restrict__ r, const float* __restrict__ Sigma,
           const float* __restrict__ sigma2,
           const float* __restrict__ w_r1, const float* __restrict__ b_r1,
           const float* __restrict__ w_r2, const float* __restrict__ b_r2,
           const float* __restrict__ w_r3, const float* __restrict__ b_r3,
           float* __restrict__ out, int layer) {
    int rd = layer & 1;
    int wr = 1 - rd;
    int last = (layer == 1);

    int b = blockIdx.y;
    int i0 = blockIdx.x * 16;
    int tid = threadIdx.x;
    int iy = tid >> 4;
    int sub = tid & 15;
    int kh = sub >> 3;
    int jx = sub & 7;
    int k0h = kh * 8;
    int i = i0 + iy;
    int nodei = b * Nc + i;

    __shared__ __align__(16) float cS[128][20];
    __shared__ float s_wih[480], s_whh[48 * 17], s_wp3[8 * 9], s_wup[8 * 17], s_wp1[288];
    __shared__ float s_bih[48], s_bhh[48], s_bp3[8], s_bup[8], s_bp1[16];
    __shared__ float s_h2s[16][8];
    __shared__ float sgin[16][10], sg[16][17], sgn[16][17], su[16][8];
    __shared__ float s_r1[128], s_br1[16], s_r2[128], s_br2[8], s_r3[32], s_br3[4];
    __shared__ float sh1[16][17];

    for (int t = tid; t < 480; t += 256) s_wih[t] = w_ih[t];
    for (int t = tid; t < 768; t += 256) s_whh[(t >> 4) * 17 + (t & 15)] = w_hh[t];
    for (int t = tid; t < 288; t += 256) s_wp1[t] = w_p1[t];
    if (tid < 128) s_wup[(tid >> 4) * 17 + (tid & 15)] = w_up[tid];
    if (tid < 64)  s_wp3[(tid >> 3) * 9 + (tid & 7)] = w_p3[tid];
    if (tid < 48)  { s_bih[tid] = b_ih[tid]; s_bhh[tid] = b_hh[tid]; }
    if (tid < 16)  s_bp1[tid] = b_p1[tid];
    if (tid < 8)   { s_bp3[tid] = b_p3[tid]; s_bup[tid] = b_up[tid]; }
    if (last) {
        if (tid < 128) { s_r1[tid] = w_r1[tid]; s_r2[tid] = w_r2[tid]; }
        if (tid < 32) s_r3[tid] = w_r3[tid];
        if (tid < 16) s_br1[tid] = b_r1[tid];
        if (tid < 8)  s_br2[tid] = b_r2[tid];
        if (tid < 4)  s_br3[tid] = b_r3[tid];
    }

    // per-thread operands (k-half only); W2 packed as f32x2 pairs
    float areg[8], w1g[8], b2r[4];
    ull W2p[8][4];
#pragma unroll
    for (int k = 0; k < 8; k++) areg[k] = g_ab[rd][nodei * 16 + k0h + k];
#pragma unroll
    for (int k = 0; k < 8; k++) w1g[k] = __ldg(&w_p1[(k0h + k) * 18 + 16]);
#pragma unroll
    for (int o = 0; o < 8; o++) {
#pragma unroll
        for (int q = 0; q < 4; q++)
            W2p[o][q] = pk2(__ldg(&w_p2[o * 16 + k0h + 2 * q]),
                            __ldg(&w_p2[o * 16 + k0h + 2 * q + 1]));
    }
#pragma unroll
    for (int o = 0; o < 4; o++) b2r[o] = __ldg(&b_p2[kh * 4 + o]);
    float acc[4] = {0.f, 0.f, 0.f, 0.f};

    const float* Grow = g_G + (size_t)b * Nc * Nc + (size_t)i * Nc;
    const float* cbase = g_cb[rd] + (size_t)(b * Nc) * 16;

    for (int jc = 0; jc < Nc; jc += 128) {
        __syncthreads();
        {
            const float4* src = (const float4*)(cbase + (size_t)jc * 16);
            float4 v0 = src[tid];
            float4 v1 = src[tid + 256];
            *(float4*)&cS[tid >> 2][(tid & 3) * 4] = v0;
            *(float4*)&cS[(tid + 256) >> 2][(tid & 3) * 4] = v1;
        }
        __syncthreads();
#pragma unroll
        for (int it = 0; it < 16; it++) {
            int jj = it * 8 + jx;
            int j = jc + jj;
            float Gv = Grow[j];
            float4 c0 = *(const float4*)&cS[jj][k0h];
            float4 c1 = *(const float4*)&cS[jj][k0h + 4];
            float cv[8] = {c0.x, c0.y, c0.z, c0.w, c1.x, c1.y, c1.z, c1.w};
            float h1[8];
#pragma unroll
            for (int k = 0; k < 8; k++)
                h1[k] = fmaxf(fmaf(w1g[k], Gv, areg[k]) + cv[k], 0.f);
            // pack h1 into 4 f32x2 operands; GEMV = 32 FFMA2 (was 64 FFMA)
            ull h1p[4];
#pragma unroll
            for (int q = 0; q < 4; q++) h1p[q] = pk2(h1[2 * q], h1[2 * q + 1]);
            float t[8];
#pragma unroll
            for (int o = 0; o < 8; o++) {
                ull t2 = 0ull;
#pragma unroll
                for (int q = 0; q < 4; q++) t2 = ffma2(W2p[o][q], h1p[q], t2);
                float2 tf = upk2(t2);
                t[o] = tf.x + tf.y;
            }
            float mask = (j == i) ? 0.f : 1.f;
#pragma unroll
            for (int o = 0; o < 4; o++) {
                float send = kh ? t[o] : t[4 + o];
                float recvv = __shfl_xor_sync(0xffffffffu, send, 8);
                float mine = kh ? t[4 + o] : t[o];
                float v = mine + recvv + b2r[o];
                acc[o] = fmaf(mask, fmaxf(v, 0.f), acc[o]);
            }
        }
    }

#pragma unroll
    for (int o = 0; o < 4; o++) {
        acc[o] += __shfl_down_sync(0xffffffffu, acc[o], 4, 8);
        acc[o] += __shfl_down_sync(0xffffffffu, acc[o], 2, 8);
        acc[o] += __shfl_down_sync(0xffffffffu, acc[o], 1, 8);
    }
    if (jx == 0) {
#pragma unroll
        for (int o = 0; o < 4; o++) s_h2s[iy][kh * 4 + o] = acc[o];
    }
    __syncthreads();

    // ================= GRU epilogue (16 thr per node) =================
    int nl = tid >> 4, t = tid & 15;
    int node = b * Nc + i0 + nl;

    sg[nl][t] = g_g[node * 16 + t];
    if (t < 8) {
        float m = s_bp3[t] * (float)(Nc - 1);
#pragma unroll
        for (int q = 0; q < 8; q++)
            m = fmaf(s_wp3[t * 9 + q], s_h2s[nl][q], m);
        sgin[nl][t] = m;
    } else if (t == 8) {
        sgin[nl][8] = r[node];
    } else if (t == 9) {
        sgin[nl][9] = Sigma[node];
    }
    __syncthreads();

    {
        float ir = s_bih[t],      hr = s_bhh[t];
        float iz = s_bih[16 + t], hz = s_bhh[16 + t];
        float in_ = s_bih[32 + t], hn = s_bhh[32 + t];
#pragma unroll
        for (int k = 0; k < 10; k++) {
            float x = sgin[nl][k];
            ir  = fmaf(s_wih[t * 10 + k],        x, ir);
            iz  = fmaf(s_wih[(16 + t) * 10 + k], x, iz);
            in_ = fmaf(s_wih[(32 + t) * 10 + k], x, in_);
        }
#pragma unroll
        for (int k = 0; k < 16; k++) {
            float x = sg[nl][k];
            hr = fmaf(s_whh[t * 17 + k],        x, hr);
            hz = fmaf(s_whh[(16 + t) * 17 + k], x, hz);
            hn = fmaf(s_whh[(32 + t) * 17 + k], x, hn);
        }
        float rr = sigmoidf_fast(ir + hr);
        float zz = sigmoidf_fast(iz + hz);
        float nn = tanhf_fast(in_ + rr * hn);
        float gv = sg[nl][t];
        float gn = (1.f - zz) * nn + zz * gv;
        sgn[nl][t] = gn;
        g_g[node * 16 + t] = gn;
    }
    __syncthreads();

    if (t < 8) {
        float uv = s_bup[t];
#pragma unroll
        for (int k = 0; k < 16; k++) uv = fmaf(s_wup[t * 17 + k], sgn[nl][k], uv);
        su[nl][t] = uv;
    }
    __syncthreads();

    if (!last) {
        float sig = sigma2[b];
        float av = s_bp1[t] + s_wp1[t * 18 + 17] * sig;
        float cv = 0.f;
#pragma unroll
        for (int k = 0; k < 8; k++) {
            float uv = su[nl][k];
            av = fmaf(s_wp1[t * 18 + k], uv, av);
            cv = fmaf(s_wp1[t * 18 + 8 + k], uv, cv);
        }
        g_ab[wr][node * 16 + t] = av;
        g_cb[wr][node * 16 + t] = cv;
    } else {
        {
            float a = s_br1[t];
#pragma unroll
            for (int k = 0; k < 8; k++) a = fmaf(s_r1[t * 8 + k], su[nl][k], a);
            sh1[nl][t] = fmaxf(a, 0.f);
        }
        __syncthreads();
        if (t < 8) {
            float a = s_br2[t];
#pragma unroll
            for (int k = 0; k < 16; k++) a = fmaf(s_r2[t * 16 + k], sh1[nl][k], a);
            sgin[nl][t] = fmaxf(a, 0.f);
        }
        __syncthreads();
        if (t == 0) {
            float lg[4];
#pragma unroll
            for (int o = 0; o < 4; o++) {
                float a = s_br3[o];
#pragma unroll
                for (int k = 0; k < 8; k++) a = fmaf(s_r3[o * 8 + k], sgin[nl][k], a);
                lg[o] = a;
            }
            float mx = fmaxf(fmaxf(lg[0], lg[1]), fmaxf(lg[2], lg[3]));
            float e0 = __expf(lg[0] - mx), e1 = __expf(lg[1] - mx),
                  e2 = __expf(lg[2] - mx), e3 = __expf(lg[3] - mx);
            float inv = __fdividef(1.f, e0 + e1 + e2 + e3);
            out[node * 4 + 0] = e0 * inv;
            out[node * 4 + 1] = e1 * inv;
            out[node * 4 + 2] = e2 * inv;
            out[node * 4 + 3] = e3 * inv;
        }
        if (t < 8) out[BNc * 4 + node * 8 + t] = su[nl][t];
        out[BNc * 12 + node * 16 + t] = sgn[nl][t];
    }
}

// ============================================================
extern "C" void kernel_launch(void* const* d_in, const int* in_sizes, int n_in,
                              void* d_out, int out_size) {
    const float* y      = (const float*)d_in[0];
    const float* A      = (const float*)d_in[1];
    const float* sigma2 = (const float*)d_in[2];
    const float* r      = (const float*)d_in[3];
    const float* Sigma  = (const float*)d_in[4];
    const float* w_init = (const float*)d_in[5];
    const float* b_init = (const float*)d_in[6];
    const float* w_p1   = (const float*)d_in[7];
    const float* b_p1   = (const float*)d_in[8];
    const float* w_p2   = (const float*)d_in[9];
    const float* b_p2   = (const float*)d_in[10];
    const float* w_p3   = (const float*)d_in[11];
    const float* b_p3   = (const float*)d_in[12];
    const float* w_ih   = (const float*)d_in[13];
    const float* b_ih   = (const float*)d_in[14];
    const float* w_hh   = (const float*)d_in[15];
    const float* b_hh   = (const float*)d_in[16];
    const float* w_up   = (const float*)d_in[17];
    const float* b_up   = (const float*)d_in[18];
    const float* w_r1   = (const float*)d_in[19];
    const float* b_r1   = (const float*)d_in[20];
    const float* w_r2   = (const float*)d_in[21];
    const float* b_r2   = (const float*)d_in[22];
    const float* w_r3   = (const float*)d_in[23];
    const float* b_r3   = (const float*)d_in[24];

    convert_kernel<<<dim3(Nc / 32, Mc / 32, Bc), dim3(32, 8)>>>(A);
    gram_mma<<<dim3(36, Bc), 256>>>();
    init_kernel<<<dim3(Nc / 128, Bc), 128>>>(A, y, sigma2, w_init, b_init, w_p1, b_p1);
    for (int l = 0; l < 2; l++) {
        pair_fused<<<dim3(Nc / 16, Bc), 256>>>(
            w_p1, b_p1, w_p2, b_p2, w_p3, b_p3, w_ih, b_ih, w_hh, b_hh,
            w_up, b_up, r, Sigma, sigma2,
            w_r1, b_r1, w_r2, b_r2, w_r3, b_r3,
            (float*)d_out, l);
    }
}

// round 13
// speedup vs baseline: 1.1333x; 1.1333x over previous
#include <cuda_runtime.h>
#include <cuda_bf16.h>
#include <math.h>

#define Bc   16
#define Mc   256
#define Nc   512
#define H1c  16
#define H2c  8
#define Uc   8
#define OUTc 4
#define BNc  (Bc*Nc)

__device__ __forceinline__ float sigmoidf_fast(float x) {
    return __fdividef(1.f, 1.f + __expf(-x));
}
__device__ __forceinline__ float tanhf_fast(float x) {
    float e = __expf(2.f * x);
    return 1.f - __fdividef(2.f, e + 1.f);
}

// ---- scratch (static device globals; no allocation) ----
__device__ float g_G[(size_t)Bc*Nc*Nc];     // 16 MB Gram
__device__ float g_g[BNc*H1c];              // GRU hidden
__device__ float g_ab[2][BNc*H1c];          // a_i per layer buffer
__device__ float g_cb[2][BNc*H1c];          // c_j per layer buffer
__device__ __nv_bfloat16 g_AThi[(size_t)Bc*Nc*Mc];  // A^T split-bf16 hi (4MB)
__device__ __nv_bfloat16 g_ATlo[(size_t)Bc*Nc*Mc];  // A^T split-bf16 lo (4MB)
__device__ float g_ATyp[8][BNc];            // ATy partials (per m-tile)

// ---- m16n8k16 bf16 mma (row.col, f32 accum) ----
__device__ __forceinline__ void mma_bf16(float d[4], const unsigned a[4],
                                         const unsigned b0, const unsigned b1) {
    asm volatile(
        "mma.sync.aligned.m16n8k16.row.col.f32.bf16.bf16.f32 "
        "{%0,%1,%2,%3}, {%4,%5,%6,%7}, {%8,%9}, {%0,%1,%2,%3};"
        : "+f"(d[0]), "+f"(d[1]), "+f"(d[2]), "+f"(d[3])
        : "r"(a[0]), "r"(a[1]), "r"(a[2]), "r"(a[3]), "r"(b0), "r"(b1));
}

__device__ __forceinline__ void ldsm4(unsigned r[4], const void* p) {
    unsigned addr = (unsigned)__cvta_generic_to_shared(p);
    asm volatile("ldmatrix.sync.aligned.m8n8.x4.shared.b16 {%0,%1,%2,%3}, [%4];"
                 : "=r"(r[0]), "=r"(r[1]), "=r"(r[2]), "=r"(r[3]) : "r"(addr));
}

// ============================================================
// K0: transpose + split A -> AT hi/lo (bf16 [B,N,M]); ALSO
// computes ATy partials for this block's 32-m slice (reuses the
// staged tile, so init_kernel never re-reads A).
// ============================================================
__global__ void __launch_bounds__(256) convert_kernel(const float* __restrict__ A,
                                                      const float* __restrict__ y) {
    int b = blockIdx.z;
    int n0 = blockIdx.x * 32, m0 = blockIdx.y * 32;
    int tx = threadIdx.x, ty = threadIdx.y;   // (32, 8)
    __shared__ float s[32][33];

    const float* Ab = A + (size_t)b * Mc * Nc;
#pragma unroll
    for (int q = 0; q < 4; q++) {
        int r = ty + q * 8;
        s[r][tx] = Ab[(size_t)(m0 + r) * Nc + n0 + tx];
    }
    __syncthreads();
    size_t base = (size_t)b * Nc * Mc;
#pragma unroll
    for (int q = 0; q < 4; q++) {
        int nl = ty + q * 8;
        float v = s[tx][nl];              // = A[m0+tx][n0+nl]
        __nv_bfloat16 hi = __float2bfloat16_rn(v);
        float hif = __bfloat162float(hi);
        __nv_bfloat16 lo = __float2bfloat16_rn(v - hif);
        size_t o = base + (size_t)(n0 + nl) * Mc + m0 + tx;
        g_AThi[o] = hi;
        g_ATlo[o] = lo;
    }
    // ATy partial: warp ty==0, thread tx handles n = n0+tx
    if (ty == 0) {
        float p = 0.f;
#pragma unroll
        for (int m = 0; m < 32; m++)
            p = fmaf(s[m][tx], __ldg(&y[b * Mc + m0 + m]), p);
        g_ATyp[blockIdx.y][b * Nc + n0 + tx] = p;
    }
}

// ============================================================
// K1: G = A^T A via split-bf16 mma (3 terms), symmetric tiles.
// (R11 proven: k-chunk 64 + reg prefetch + ldmatrix; unchanged)
// ============================================================
__global__ void __launch_bounds__(256) gram_mma(void) {
    int b = blockIdx.y;
    int idx = blockIdx.x;                 // 0..35 -> (ti<=tj)
    int ti = 0;
    while (idx >= 8 - ti) { idx -= 8 - ti; ti++; }
    int tj = ti + idx;
    int i0 = ti * 64, j0 = tj * 64;

    int tid = threadIdx.x;
    int w = tid >> 5, lane = tid & 31;
    int g = lane >> 2, t2 = (lane & 3) * 2;
    int wr = w >> 2, wc = w & 3;          // warp tile: i = wr*32.., j = wc*16..

    __shared__ __align__(16) unsigned char sraw[4 * 64 * 72 * 2];
    unsigned short (*TIh)[72] = (unsigned short(*)[72])(sraw);
    unsigned short (*TIl)[72] = (unsigned short(*)[72])(sraw + 9216);
    unsigned short (*TJh)[72] = (unsigned short(*)[72])(sraw + 18432);
    unsigned short (*TJl)[72] = (unsigned short(*)[72])(sraw + 27648);
    float (*Ds)[67] = (float(*)[67])(sraw);   // overlay AFTER compute

    const unsigned short* ATh = (const unsigned short*)g_AThi + (size_t)b * Nc * Mc;
    const unsigned short* ATl = (const unsigned short*)g_ATlo + (size_t)b * Nc * Mc;

    float D[2][2][4];
#pragma unroll
    for (int mi = 0; mi < 2; mi++)
#pragma unroll
        for (int nj = 0; nj < 2; nj++)
#pragma unroll
            for (int q = 0; q < 4; q++) D[mi][nj][q] = 0.f;

    int tilesel = tid >> 6;
    int r2 = tid & 63;
    int hh = r2 & 7;
    int rb = r2 >> 3;
    const unsigned short* srcb = ((tilesel & 1) == 0) ? ATh : ATl;
    int rbase = (tilesel < 2) ? i0 : j0;
    unsigned short (*dstt)[72] =
        (tilesel == 0) ? TIh : (tilesel == 1) ? TIl : (tilesel == 2) ? TJh : TJl;

    int lrow = (lane & 7) + ((lane >> 3) & 1) * 8;
    int lcol = (lane >> 4) * 8;

    uint4 buf[8];
#pragma unroll
    for (int q = 0; q < 8; q++)
        buf[q] = *(const uint4*)&srcb[(size_t)(rbase + rb + q * 8) * Mc + hh * 8];

    for (int c = 0; c < 4; c++) {
        __syncthreads();
#pragma unroll
        for (int q = 0; q < 8; q++)
            *(uint4*)&dstt[rb + q * 8][hh * 8] = buf[q];
        __syncthreads();
        if (c < 3) {
            int cnext = (c + 1) * 64;
#pragma unroll
            for (int q = 0; q < 8; q++)
                buf[q] = *(const uint4*)&srcb[(size_t)(rbase + rb + q * 8) * Mc
                                              + cnext + hh * 8];
        }
#pragma unroll
        for (int kk = 0; kk < 4; kk++) {
            int kc = kk * 16 + lcol;
            unsigned Ah[2][4], Al[2][4], Bh[4], Bl[4];
#pragma unroll
            for (int mi = 0; mi < 2; mi++) {
                ldsm4(Ah[mi], &TIh[wr * 32 + mi * 16 + lrow][kc]);
                ldsm4(Al[mi], &TIl[wr * 32 + mi * 16 + lrow][kc]);
            }
            ldsm4(Bh, &TJh[wc * 16 + lrow][kc]);
            ldsm4(Bl, &TJl[wc * 16 + lrow][kc]);
#pragma unroll
            for (int mi = 0; mi < 2; mi++) {
                mma_bf16(D[mi][0], Ah[mi], Bh[0], Bh[2]);
                mma_bf16(D[mi][0], Ah[mi], Bl[0], Bl[2]);
                mma_bf16(D[mi][0], Al[mi], Bh[0], Bh[2]);
                mma_bf16(D[mi][1], Ah[mi], Bh[1], Bh[3]);
                mma_bf16(D[mi][1], Ah[mi], Bl[1], Bl[3]);
                mma_bf16(D[mi][1], Al[mi], Bh[1], Bh[3]);
            }
        }
    }

    __syncthreads();
#pragma unroll
    for (int mi = 0; mi < 2; mi++)
#pragma unroll
        for (int nj = 0; nj < 2; nj++) {
            int rr = wr * 32 + mi * 16 + g;
            int cc = wc * 16 + nj * 8 + t2;
            Ds[rr][cc]     = D[mi][nj][0];
            Ds[rr][cc + 1] = D[mi][nj][1];
            Ds[rr + 8][cc]     = D[mi][nj][2];
            Ds[rr + 8][cc + 1] = D[mi][nj][3];
        }
    __syncthreads();

    float* Gb = g_G + (size_t)b * Nc * Nc;
    int r = tid >> 2, c0 = (tid & 3) * 16;
#pragma unroll
    for (int q = 0; q < 4; q++) {
        float4 v = make_float4(Ds[r][c0 + q * 4], Ds[r][c0 + q * 4 + 1],
                               Ds[r][c0 + q * 4 + 2], Ds[r][c0 + q * 4 + 3]);
        *(float4*)(Gb + (size_t)(i0 + r) * Nc + j0 + c0 + q * 4) = v;
    }
    if (ti != tj) {
#pragma unroll
        for (int q = 0; q < 4; q++) {
            float4 v = make_float4(Ds[c0 + q * 4][r], Ds[c0 + q * 4 + 1][r],
                                   Ds[c0 + q * 4 + 2][r], Ds[c0 + q * 4 + 3][r]);
            *(float4*)(Gb + (size_t)(j0 + r) * Nc + i0 + c0 + q * 4) = v;
        }
    }
}

// ============================================================
// K2: sum ATy partials, diag(G), u0; zero g; a,c -> buffer 0.
// (no longer reads A)
// ============================================================
__global__ void init_kernel(const float* __restrict__ sigma2,
                            const float* __restrict__ w_init, const float* __restrict__ b_init,
                            const float* __restrict__ w_p1, const float* __restrict__ b_p1) {
    int b = blockIdx.y;
    int n = blockIdx.x * 128 + threadIdx.x;
    int node = b * Nc + n;

    float aty = 0.f;
#pragma unroll
    for (int p = 0; p < 8; p++) aty += g_ATyp[p][node];

    float diag = g_G[(size_t)b * Nc * Nc + (size_t)n * Nc + n];
    float sig = sigma2[b];

    float u[Uc];
#pragma unroll
    for (int o = 0; o < Uc; o++) {
        u[o] = b_init[o] + w_init[o * 3 + 0] * aty + w_init[o * 3 + 1] * diag
             + w_init[o * 3 + 2] * sig;
    }
#pragma unroll
    for (int k = 0; k < H1c; k++) g_g[node * H1c + k] = 0.f;

#pragma unroll
    for (int o = 0; o < H1c; o++) {
        float av = b_p1[o] + w_p1[o * 18 + 17] * sig;
        float cv = 0.f;
#pragma unroll
        for (int k = 0; k < Uc; k++) {
            av = fmaf(w_p1[o * 18 + k], u[k], av);
            cv = fmaf(w_p1[o * 18 + 8 + k], u[k], cv);
        }
        g_ab[0][node * H1c + o] = av;
        g_cb[0][node * H1c + o] = cv;
    }
}

// ============================================================
// K3: fused pair + GRU (+ readout on last layer).
// (R9/R11 proven scalar version — reverted from f32x2)
// ============================================================
__global__ void __launch_bounds__(256, 2)
pair_fused(const float* __restrict__ w_p1, const float* __restrict__ b_p1,
           const float* __restrict__ w_p2, const float* __restrict__ b_p2,
           const float* __restrict__ w_p3, const float* __restrict__ b_p3,
           const float* __restrict__ w_ih, const float* __restrict__ b_ih,
           const float* __restrict__ w_hh, const float* __restrict__ b_hh,
           const float* __restrict__ w_up, const float* __restrict__ b_up,
           const float* __restrict__ r, const float* __restrict__ Sigma,
           const float* __restrict__ sigma2,
           const float* __restrict__ w_r1, const float* __restrict__ b_r1,
           const float* __restrict__ w_r2, const float* __restrict__ b_r2,
           const float* __restrict__ w_r3, const float* __restrict__ b_r3,
           float* __restrict__ out, int layer) {
    int rd = layer & 1;
    int wr = 1 - rd;
    int last = (layer == 1);

    int b = blockIdx.y;
    int i0 = blockIdx.x * 16;
    int tid = threadIdx.x;
    int iy = tid >> 4;
    int sub = tid & 15;
    int kh = sub >> 3;
    int jx = sub & 7;
    int k0h = kh * 8;
    int i = i0 + iy;
    int nodei = b * Nc + i;

    __shared__ __align__(16) float cS[128][20];
    __shared__ float s_wih[480], s_whh[48 * 17], s_wp3[8 * 9], s_wup[8 * 17], s_wp1[288];
    __shared__ float s_bih[48], s_bhh[48], s_bp3[8], s_bup[8], s_bp1[16];
    __shared__ float s_h2s[16][8];
    __shared__ float sgin[16][10], sg[16][17], sgn[16][17], su[16][8];
    __shared__ float s_r1[128], s_br1[16], s_r2[128], s_br2[8], s_r3[32], s_br3[4];
    __shared__ float sh1[16][17];

    for (int t = tid; t < 480; t += 256) s_wih[t] = w_ih[t];
    for (int t = tid; t < 768; t += 256) s_whh[(t >> 4) * 17 + (t & 15)] = w_hh[t];
    for (int t = tid; t < 288; t += 256) s_wp1[t] = w_p1[t];
    if (tid < 128) s_wup[(tid >> 4) * 17 + (tid & 15)] = w_up[tid];
    if (tid < 64)  s_wp3[(tid >> 3) * 9 + (tid & 7)] = w_p3[tid];
    if (tid < 48)  { s_bih[tid] = b_ih[tid]; s_bhh[tid] = b_hh[tid]; }
    if (tid < 16)  s_bp1[tid] = b_p1[tid];
    if (tid < 8)   { s_bp3[tid] = b_p3[tid]; s_bup[tid] = b_up[tid]; }
    if (last) {
        if (tid < 128) { s_r1[tid] = w_r1[tid]; s_r2[tid] = w_r2[tid]; }
        if (tid < 32) s_r3[tid] = w_r3[tid];
        if (tid < 16) s_br1[tid] = b_r1[tid];
        if (tid < 8)  s_br2[tid] = b_r2[tid];
        if (tid < 4)  s_br3[tid] = b_r3[tid];
    }

    float areg[8], w1g[8], W2h[8][8], b2r[4];
#pragma unroll
    for (int k = 0; k < 8; k++) areg[k] = g_ab[rd][nodei * 16 + k0h + k];
#pragma unroll
    for (int k = 0; k < 8; k++) w1g[k] = __ldg(&w_p1[(k0h + k) * 18 + 16]);
#pragma unroll
    for (int o = 0; o < 8; o++) {
#pragma unroll
        for (int k = 0; k < 8; k++) W2h[o][k] = __ldg(&w_p2[o * 16 + k0h + k]);
    }
#pragma unroll
    for (int o = 0; o < 4; o++) b2r[o] = __ldg(&b_p2[kh * 4 + o]);
    float acc[4] = {0.f, 0.f, 0.f, 0.f};

    const float* Grow = g_G + (size_t)b * Nc * Nc + (size_t)i * Nc;
    const float* cbase = g_cb[rd] + (size_t)(b * Nc) * 16;

    for (int jc = 0; jc < Nc; jc += 128) {
        __syncthreads();
        {
            const float4* src = (const float4*)(cbase + (size_t)jc * 16);
            float4 v0 = src[tid];
            float4 v1 = src[tid + 256];
            *(float4*)&cS[tid >> 2][(tid & 3) * 4] = v0;
            *(float4*)&cS[(tid + 256) >> 2][(tid & 3) * 4] = v1;
        }
        __syncthreads();
#pragma unroll
        for (int it = 0; it < 16; it++) {
            int jj = it * 8 + jx;
            int j = jc + jj;
            float Gv = Grow[j];
            float4 c0 = *(const float4*)&cS[jj][k0h];
            float4 c1 = *(const float4*)&cS[jj][k0h + 4];
            float cv[8] = {c0.x, c0.y, c0.z, c0.w, c1.x, c1.y, c1.z, c1.w};
            float h1[8];
#pragma unroll
            for (int k = 0; k < 8; k++)
                h1[k] = fmaxf(fmaf(w1g[k], Gv, areg[k]) + cv[k], 0.f);
            float t[8];
#pragma unroll
            for (int o = 0; o < 8; o++) {
                float s_ = 0.f;
#pragma unroll
                for (int k = 0; k < 8; k++) s_ = fmaf(W2h[o][k], h1[k], s_);
                t[o] = s_;
            }
            float mask = (j == i) ? 0.f : 1.f;
#pragma unroll
            for (int o = 0; o < 4; o++) {
                float send = kh ? t[o] : t[4 + o];
                float recvv = __shfl_xor_sync(0xffffffffu, send, 8);
                float mine = kh ? t[4 + o] : t[o];
                float v = mine + recvv + b2r[o];
                acc[o] = fmaf(mask, fmaxf(v, 0.f), acc[o]);
            }
        }
    }

#pragma unroll
    for (int o = 0; o < 4; o++) {
        acc[o] += __shfl_down_sync(0xffffffffu, acc[o], 4, 8);
        acc[o] += __shfl_down_sync(0xffffffffu, acc[o], 2, 8);
        acc[o] += __shfl_down_sync(0xffffffffu, acc[o], 1, 8);
    }
    if (jx == 0) {
#pragma unroll
        for (int o = 0; o < 4; o++) s_h2s[iy][kh * 4 + o] = acc[o];
    }
    __syncthreads();

    // ================= GRU epilogue (16 thr per node) =================
    int nl = tid >> 4, t = tid & 15;
    int node = b * Nc + i0 + nl;

    sg[nl][t] = g_g[node * 16 + t];
    if (t < 8) {
        float m = s_bp3[t] * (float)(Nc - 1);
#pragma unroll
        for (int q = 0; q < 8; q++)
            m = fmaf(s_wp3[t * 9 + q], s_h2s[nl][q], m);
        sgin[nl][t] = m;
    } else if (t == 8) {
        sgin[nl][8] = r[node];
    } else if (t == 9) {
        sgin[nl][9] = Sigma[node];
    }
    __syncthreads();

    {
        float ir = s_bih[t],      hr = s_bhh[t];
        float iz = s_bih[16 + t], hz = s_bhh[16 + t];
        float in_ = s_bih[32 + t], hn = s_bhh[32 + t];
#pragma unroll
        for (int k = 0; k < 10; k++) {
            float x = sgin[nl][k];
            ir  = fmaf(s_wih[t * 10 + k],        x, ir);
            iz  = fmaf(s_wih[(16 + t) * 10 + k], x, iz);
            in_ = fmaf(s_wih[(32 + t) * 10 + k], x, in_);
        }
#pragma unroll
        for (int k = 0; k < 16; k++) {
            float x = sg[nl][k];
            hr = fmaf(s_whh[t * 17 + k],        x, hr);
            hz = fmaf(s_whh[(16 + t) * 17 + k], x, hz);
            hn = fmaf(s_whh[(32 + t) * 17 + k], x, hn);
        }
        float rr = sigmoidf_fast(ir + hr);
        float zz = sigmoidf_fast(iz + hz);
        float nn = tanhf_fast(in_ + rr * hn);
        float gv = sg[nl][t];
        float gn = (1.f - zz) * nn + zz * gv;
        sgn[nl][t] = gn;
        g_g[node * 16 + t] = gn;
    }
    __syncthreads();

    if (t < 8) {
        float uv = s_bup[t];
#pragma unroll
        for (int k = 0; k < 16; k++) uv = fmaf(s_wup[t * 17 + k], sgn[nl][k], uv);
        su[nl][t] = uv;
    }
    __syncthreads();

    if (!last) {
        float sig = sigma2[b];
        float av = s_bp1[t] + s_wp1[t * 18 + 17] * sig;
        float cv = 0.f;
#pragma unroll
        for (int k = 0; k < 8; k++) {
            float uv = su[nl][k];
            av = fmaf(s_wp1[t * 18 + k], uv, av);
            cv = fmaf(s_wp1[t * 18 + 8 + k], uv, cv);
        }
        g_ab[wr][node * 16 + t] = av;
        g_cb[wr][node * 16 + t] = cv;
    } else {
        {
            float a = s_br1[t];
#pragma unroll
            for (int k = 0; k < 8; k++) a = fmaf(s_r1[t * 8 + k], su[nl][k], a);
            sh1[nl][t] = fmaxf(a, 0.f);
        }
        __syncthreads();
        if (t < 8) {
            float a = s_br2[t];
#pragma unroll
            for (int k = 0; k < 16; k++) a = fmaf(s_r2[t * 16 + k], sh1[nl][k], a);
            sgin[nl][t] = fmaxf(a, 0.f);
        }
        __syncthreads();
        if (t == 0) {
            float lg[4];
#pragma unroll
            for (int o = 0; o < 4; o++) {
                float a = s_br3[o];
#pragma unroll
                for (int k = 0; k < 8; k++) a = fmaf(s_r3[o * 8 + k], sgin[nl][k], a);
                lg[o] = a;
            }
            float mx = fmaxf(fmaxf(lg[0], lg[1]), fmaxf(lg[2], lg[3]));
            float e0 = __expf(lg[0] - mx), e1 = __expf(lg[1] - mx),
                  e2 = __expf(lg[2] - mx), e3 = __expf(lg[3] - mx);
            float inv = __fdividef(1.f, e0 + e1 + e2 + e3);
            out[node * 4 + 0] = e0 * inv;
            out[node * 4 + 1] = e1 * inv;
            out[node * 4 + 2] = e2 * inv;
            out[node * 4 + 3] = e3 * inv;
        }
        if (t < 8) out[BNc * 4 + node * 8 + t] = su[nl][t];
        out[BNc * 12 + node * 16 + t] = sgn[nl][t];
    }
}

// ============================================================
extern "C" void kernel_launch(void* const* d_in, const int* in_sizes, int n_in,
                              void* d_out, int out_size) {
    const float* y      = (const float*)d_in[0];
    const float* A      = (const float*)d_in[1];
    const float* sigma2 = (const float*)d_in[2];
    const float* r      = (const float*)d_in[3];
    const float* Sigma  = (const float*)d_in[4];
    const float* w_init = (const float*)d_in[5];
    const float* b_init = (const float*)d_in[6];
    const float* w_p1   = (const float*)d_in[7];
    const float* b_p1   = (const float*)d_in[8];
    const float* w_p2   = (const float*)d_in[9];
    const float* b_p2   = (const float*)d_in[10];
    const float* w_p3   = (const float*)d_in[11];
    const float* b_p3   = (const float*)d_in[12];
    const float* w_ih   = (const float*)d_in[13];
    const float* b_ih   = (const float*)d_in[14];
    const float* w_hh   = (const float*)d_in[15];
    const float* b_hh   = (const float*)d_in[16];
    const float* w_up   = (const float*)d_in[17];
    const float* b_up   = (const float*)d_in[18];
    const float* w_r1   = (const float*)d_in[19];
    const float* b_r1   = (const float*)d_in[20];
    const float* w_r2   = (const float*)d_in[21];
    const float* b_r2   = (const float*)d_in[22];
    const float* w_r3   = (const float*)d_in[23];
    const float* b_r3   = (const float*)d_in[24];

    convert_kernel<<<dim3(Nc / 32, Mc / 32, Bc), dim3(32, 8)>>>(A, y);
    gram_mma<<<dim3(36, Bc), 256>>>();
    init_kernel<<<dim3(Nc / 128, Bc), 128>>>(sigma2, w_init, b_init, w_p1, b_p1);
    for (int l = 0; l < 2; l++) {
        pair_fused<<<dim3(Nc / 16, Bc), 256>>>(
            w_p1, b_p1, w_p2, b_p2, w_p3, b_p3, w_ih, b_ih, w_hh, b_hh,
            w_up, b_up, r, Sigma, sigma2,
            w_r1, b_r1, w_r2, b_r2, w_r3, b_r3,
            (float*)d_out, l);
    }
}

// round 14
// speedup vs baseline: 1.2199x; 1.0764x over previous
#include <cuda_runtime.h>
#include <cuda_bf16.h>
#include <cuda_fp16.h>
#include <math.h>

#define Bc   16
#define Mc   256
#define Nc   512
#define H1c  16
#define H2c  8
#define Uc   8
#define OUTc 4
#define BNc  (Bc*Nc)

__device__ __forceinline__ float sigmoidf_fast(float x) {
    return __fdividef(1.f, 1.f + __expf(-x));
}
__device__ __forceinline__ float tanhf_fast(float x) {
    float e = __expf(2.f * x);
    return 1.f - __fdividef(2.f, e + 1.f);
}
__device__ __forceinline__ unsigned h2u(__half2 v) {
    unsigned u; *(__half2*)&u = v; return u;
}
__device__ __forceinline__ __half2 u2h(unsigned u) {
    return *(__half2*)&u;
}

// ---- scratch (static device globals; no allocation) ----
__device__ float g_G[(size_t)Bc*Nc*Nc];     // 16 MB Gram
__device__ float g_g[BNc*H1c];              // GRU hidden
__device__ float g_ab[2][BNc*H1c];          // a_i per layer buffer
__device__ float g_cb[2][BNc*H1c];          // c_j per layer buffer
__device__ __nv_bfloat16 g_AThi[(size_t)Bc*Nc*Mc];  // A^T split-bf16 hi (4MB)
__device__ __nv_bfloat16 g_ATlo[(size_t)Bc*Nc*Mc];  // A^T split-bf16 lo (4MB)
__device__ float g_ATyp[8][BNc];            // ATy partials (per m-tile)

// ---- m16n8k16 bf16 mma (row.col, f32 accum) ----
__device__ __forceinline__ void mma_bf16(float d[4], const unsigned a[4],
                                         const unsigned b0, const unsigned b1) {
    asm volatile(
        "mma.sync.aligned.m16n8k16.row.col.f32.bf16.bf16.f32 "
        "{%0,%1,%2,%3}, {%4,%5,%6,%7}, {%8,%9}, {%0,%1,%2,%3};"
        : "+f"(d[0]), "+f"(d[1]), "+f"(d[2]), "+f"(d[3])
        : "r"(a[0]), "r"(a[1]), "r"(a[2]), "r"(a[3]), "r"(b0), "r"(b1));
}

__device__ __forceinline__ void ldsm4(unsigned r[4], const void* p) {
    unsigned addr = (unsigned)__cvta_generic_to_shared(p);
    asm volatile("ldmatrix.sync.aligned.m8n8.x4.shared.b16 {%0,%1,%2,%3}, [%4];"
                 : "=r"(r[0]), "=r"(r[1]), "=r"(r[2]), "=r"(r[3]) : "r"(addr));
}

// ============================================================
// K0: transpose + split A -> AT hi/lo (bf16 [B,N,M]); also ATy
// partials from the staged tile. (R13 proven, unchanged)
// ============================================================
__global__ void __launch_bounds__(256) convert_kernel(const float* __restrict__ A,
                                                      const float* __restrict__ y) {
    int b = blockIdx.z;
    int n0 = blockIdx.x * 32, m0 = blockIdx.y * 32;
    int tx = threadIdx.x, ty = threadIdx.y;   // (32, 8)
    __shared__ float s[32][33];

    const float* Ab = A + (size_t)b * Mc * Nc;
#pragma unroll
    for (int q = 0; q < 4; q++) {
        int r = ty + q * 8;
        s[r][tx] = Ab[(size_t)(m0 + r) * Nc + n0 + tx];
    }
    __syncthreads();
    size_t base = (size_t)b * Nc * Mc;
#pragma unroll
    for (int q = 0; q < 4; q++) {
        int nl = ty + q * 8;
        float v = s[tx][nl];              // = A[m0+tx][n0+nl]
        __nv_bfloat16 hi = __float2bfloat16_rn(v);
        float hif = __bfloat162float(hi);
        __nv_bfloat16 lo = __float2bfloat16_rn(v - hif);
        size_t o = base + (size_t)(n0 + nl) * Mc + m0 + tx;
        g_AThi[o] = hi;
        g_ATlo[o] = lo;
    }
    if (ty == 0) {
        float p = 0.f;
#pragma unroll
        for (int m = 0; m < 32; m++)
            p = fmaf(s[m][tx], __ldg(&y[b * Mc + m0 + m]), p);
        g_ATyp[blockIdx.y][b * Nc + n0 + tx] = p;
    }
}

// ============================================================
// K1: G = A^T A via split-bf16 mma (3 terms), symmetric tiles.
// (R11 proven: k-chunk 64 + reg prefetch + ldmatrix; unchanged)
// ============================================================
__global__ void __launch_bounds__(256) gram_mma(void) {
    int b = blockIdx.y;
    int idx = blockIdx.x;                 // 0..35 -> (ti<=tj)
    int ti = 0;
    while (idx >= 8 - ti) { idx -= 8 - ti; ti++; }
    int tj = ti + idx;
    int i0 = ti * 64, j0 = tj * 64;

    int tid = threadIdx.x;
    int w = tid >> 5, lane = tid & 31;
    int g = lane >> 2, t2 = (lane & 3) * 2;
    int wr = w >> 2, wc = w & 3;

    __shared__ __align__(16) unsigned char sraw[4 * 64 * 72 * 2];
    unsigned short (*TIh)[72] = (unsigned short(*)[72])(sraw);
    unsigned short (*TIl)[72] = (unsigned short(*)[72])(sraw + 9216);
    unsigned short (*TJh)[72] = (unsigned short(*)[72])(sraw + 18432);
    unsigned short (*TJl)[72] = (unsigned short(*)[72])(sraw + 27648);
    float (*Ds)[67] = (float(*)[67])(sraw);

    const unsigned short* ATh = (const unsigned short*)g_AThi + (size_t)b * Nc * Mc;
    const unsigned short* ATl = (const unsigned short*)g_ATlo + (size_t)b * Nc * Mc;

    float D[2][2][4];
#pragma unroll
    for (int mi = 0; mi < 2; mi++)
#pragma unroll
        for (int nj = 0; nj < 2; nj++)
#pragma unroll
            for (int q = 0; q < 4; q++) D[mi][nj][q] = 0.f;

    int tilesel = tid >> 6;
    int r2 = tid & 63;
    int hh = r2 & 7;
    int rb = r2 >> 3;
    const unsigned short* srcb = ((tilesel & 1) == 0) ? ATh : ATl;
    int rbase = (tilesel < 2) ? i0 : j0;
    unsigned short (*dstt)[72] =
        (tilesel == 0) ? TIh : (tilesel == 1) ? TIl : (tilesel == 2) ? TJh : TJl;

    int lrow = (lane & 7) + ((lane >> 3) & 1) * 8;
    int lcol = (lane >> 4) * 8;

    uint4 buf[8];
#pragma unroll
    for (int q = 0; q < 8; q++)
        buf[q] = *(const uint4*)&srcb[(size_t)(rbase + rb + q * 8) * Mc + hh * 8];

    for (int c = 0; c < 4; c++) {
        __syncthreads();
#pragma unroll
        for (int q = 0; q < 8; q++)
            *(uint4*)&dstt[rb + q * 8][hh * 8] = buf[q];
        __syncthreads();
        if (c < 3) {
            int cnext = (c + 1) * 64;
#pragma unroll
            for (int q = 0; q < 8; q++)
                buf[q] = *(const uint4*)&srcb[(size_t)(rbase + rb + q * 8) * Mc
                                              + cnext + hh * 8];
        }
#pragma unroll
        for (int kk = 0; kk < 4; kk++) {
            int kc = kk * 16 + lcol;
            unsigned Ah[2][4], Al[2][4], Bh[4], Bl[4];
#pragma unroll
            for (int mi = 0; mi < 2; mi++) {
                ldsm4(Ah[mi], &TIh[wr * 32 + mi * 16 + lrow][kc]);
                ldsm4(Al[mi], &TIl[wr * 32 + mi * 16 + lrow][kc]);
            }
            ldsm4(Bh, &TJh[wc * 16 + lrow][kc]);
            ldsm4(Bl, &TJl[wc * 16 + lrow][kc]);
#pragma unroll
            for (int mi = 0; mi < 2; mi++) {
                mma_bf16(D[mi][0], Ah[mi], Bh[0], Bh[2]);
                mma_bf16(D[mi][0], Ah[mi], Bl[0], Bl[2]);
                mma_bf16(D[mi][0], Al[mi], Bh[0], Bh[2]);
                mma_bf16(D[mi][1], Ah[mi], Bh[1], Bh[3]);
                mma_bf16(D[mi][1], Ah[mi], Bl[1], Bl[3]);
                mma_bf16(D[mi][1], Al[mi], Bh[1], Bh[3]);
            }
        }
    }

    __syncthreads();
#pragma unroll
    for (int mi = 0; mi < 2; mi++)
#pragma unroll
        for (int nj = 0; nj < 2; nj++) {
            int rr = wr * 32 + mi * 16 + g;
            int cc = wc * 16 + nj * 8 + t2;
            Ds[rr][cc]     = D[mi][nj][0];
            Ds[rr][cc + 1] = D[mi][nj][1];
            Ds[rr + 8][cc]     = D[mi][nj][2];
            Ds[rr + 8][cc + 1] = D[mi][nj][3];
        }
    __syncthreads();

    float* Gb = g_G + (size_t)b * Nc * Nc;
    int r = tid >> 2, c0 = (tid & 3) * 16;
#pragma unroll
    for (int q = 0; q < 4; q++) {
        float4 v = make_float4(Ds[r][c0 + q * 4], Ds[r][c0 + q * 4 + 1],
                               Ds[r][c0 + q * 4 + 2], Ds[r][c0 + q * 4 + 3]);
        *(float4*)(Gb + (size_t)(i0 + r) * Nc + j0 + c0 + q * 4) = v;
    }
    if (ti != tj) {
#pragma unroll
        for (int q = 0; q < 4; q++) {
            float4 v = make_float4(Ds[c0 + q * 4][r], Ds[c0 + q * 4 + 1][r],
                                   Ds[c0 + q * 4 + 2][r], Ds[c0 + q * 4 + 3][r]);
            *(float4*)(Gb + (size_t)(j0 + r) * Nc + i0 + c0 + q * 4) = v;
        }
    }
}

// ============================================================
// K2: sum ATy partials, diag(G), u0; zero g; a,c -> buffer 0.
// ============================================================
__global__ void init_kernel(const float* __restrict__ sigma2,
                            const float* __restrict__ w_init, const float* __restrict__ b_init,
                            const float* __restrict__ w_p1, const float* __restrict__ b_p1) {
    int b = blockIdx.y;
    int n = blockIdx.x * 128 + threadIdx.x;
    int node = b * Nc + n;

    float aty = 0.f;
#pragma unroll
    for (int p = 0; p < 8; p++) aty += g_ATyp[p][node];

    float diag = g_G[(size_t)b * Nc * Nc + (size_t)n * Nc + n];
    float sig = sigma2[b];

    float u[Uc];
#pragma unroll
    for (int o = 0; o < Uc; o++) {
        u[o] = b_init[o] + w_init[o * 3 + 0] * aty + w_init[o * 3 + 1] * diag
             + w_init[o * 3 + 2] * sig;
    }
#pragma unroll
    for (int k = 0; k < H1c; k++) g_g[node * H1c + k] = 0.f;

#pragma unroll
    for (int o = 0; o < H1c; o++) {
        float av = b_p1[o] + w_p1[o * 18 + 17] * sig;
        float cv = 0.f;
#pragma unroll
        for (int k = 0; k < Uc; k++) {
            av = fmaf(w_p1[o * 18 + k], u[k], av);
            cv = fmaf(w_p1[o * 18 + 8 + k], u[k], cv);
        }
        g_ab[0][node * H1c + o] = av;
        g_cb[0][node * H1c + o] = cv;
    }
}

// ============================================================
// K3: fused pair + GRU (+ readout on last layer).
// R13 layout; the 8x8 GEMV now in HFMA2 (output-pair packing:
// accumulator half2 lane = one complete output; h1 dup-packed).
// h1 stays fp32. Exchange operates on half2 (2 shfl).
// ============================================================
__global__ void __launch_bounds__(256, 2)
pair_fused(const float* __restrict__ w_p1, const float* __restrict__ b_p1,
           const float* __restrict__ w_p2, const float* __restrict__ b_p2,
           const float* __restrict__ w_p3, const float* __restrict__ b_p3,
           const float* __restrict__ w_ih, const float* __restrict__ b_ih,
           const float* __restrict__ w_hh, const float* __restrict__ b_hh,
           const float* __restrict__ w_up, const float* __restrict__ b_up,
           const float* __restrict__ r, const float* __restrict__ Sigma,
           const float* __restrict__ sigma2,
           const float* __restrict__ w_r1, const float* __restrict__ b_r1,
           const float* __restrict__ w_r2, const float* __restrict__ b_r2,
           const float* __restrict__ w_r3, const float* __restrict__ b_r3,
           float* __restrict__ out, int layer) {
    int rd = layer & 1;
    int wr = 1 - rd;
    int last = (layer == 1);

    int b = blockIdx.y;
    int i0 = blockIdx.x * 16;
    int tid = threadIdx.x;
    int iy = tid >> 4;
    int sub = tid & 15;
    int kh = sub >> 3;
    int jx = sub & 7;
    int k0h = kh * 8;
    int i = i0 + iy;
    int nodei = b * Nc + i;

    __shared__ __align__(16) float cS[128][20];
    __shared__ float s_wih[480], s_whh[48 * 17], s_wp3[8 * 9], s_wup[8 * 17], s_wp1[288];
    __shared__ float s_bih[48], s_bhh[48], s_bp3[8], s_bup[8], s_bp1[16];
    __shared__ float s_h2s[16][8];
    __shared__ float sgin[16][10], sg[16][17], sgn[16][17], su[16][8];
    __shared__ float s_r1[128], s_br1[16], s_r2[128], s_br2[8], s_r3[32], s_br3[4];
    __shared__ float sh1[16][17];

    for (int t = tid; t < 480; t += 256) s_wih[t] = w_ih[t];
    for (int t = tid; t < 768; t += 256) s_whh[(t >> 4) * 17 + (t & 15)] = w_hh[t];
    for (int t = tid; t < 288; t += 256) s_wp1[t] = w_p1[t];
    if (tid < 128) s_wup[(tid >> 4) * 17 + (tid & 15)] = w_up[tid];
    if (tid < 64)  s_wp3[(tid >> 3) * 9 + (tid & 7)] = w_p3[tid];
    if (tid < 48)  { s_bih[tid] = b_ih[tid]; s_bhh[tid] = b_hh[tid]; }
    if (tid < 16)  s_bp1[tid] = b_p1[tid];
    if (tid < 8)   { s_bp3[tid] = b_p3[tid]; s_bup[tid] = b_up[tid]; }
    if (last) {
        if (tid < 128) { s_r1[tid] = w_r1[tid]; s_r2[tid] = w_r2[tid]; }
        if (tid < 32) s_r3[tid] = w_r3[tid];
        if (tid < 16) s_br1[tid] = b_r1[tid];
        if (tid < 8)  s_br2[tid] = b_r2[tid];
        if (tid < 4)  s_br3[tid] = b_r3[tid];
    }

    // per-thread operands (k-half only); W2 as half2 output pairs:
    // W2d[op][k] = (W2[2op][k0h+k], W2[2op+1][k0h+k])
    float areg[8], w1g[8];
    __half2 W2d[4][8], b2h[2];
#pragma unroll
    for (int k = 0; k < 8; k++) areg[k] = g_ab[rd][nodei * 16 + k0h + k];
#pragma unroll
    for (int k = 0; k < 8; k++) w1g[k] = __ldg(&w_p1[(k0h + k) * 18 + 16]);
#pragma unroll
    for (int op = 0; op < 4; op++)
#pragma unroll
        for (int k = 0; k < 8; k++)
            W2d[op][k] = __floats2half2_rn(__ldg(&w_p2[(2 * op) * 16 + k0h + k]),
                                           __ldg(&w_p2[(2 * op + 1) * 16 + k0h + k]));
#pragma unroll
    for (int q = 0; q < 2; q++)
        b2h[q] = __floats2half2_rn(__ldg(&b_p2[kh * 4 + 2 * q]),
                                   __ldg(&b_p2[kh * 4 + 2 * q + 1]));
    const __half2 zero2 = __float2half2_rn(0.f);
    float acc[4] = {0.f, 0.f, 0.f, 0.f};

    const float* Grow = g_G + (size_t)b * Nc * Nc + (size_t)i * Nc;
    const float* cbase = g_cb[rd] + (size_t)(b * Nc) * 16;

    for (int jc = 0; jc < Nc; jc += 128) {
        __syncthreads();
        {
            const float4* src = (const float4*)(cbase + (size_t)jc * 16);
            float4 v0 = src[tid];
            float4 v1 = src[tid + 256];
            *(float4*)&cS[tid >> 2][(tid & 3) * 4] = v0;
            *(float4*)&cS[(tid + 256) >> 2][(tid & 3) * 4] = v1;
        }
        __syncthreads();
#pragma unroll
        for (int it = 0; it < 16; it++) {
            int jj = it * 8 + jx;
            int j = jc + jj;
            float Gv = Grow[j];
            float4 c0 = *(const float4*)&cS[jj][k0h];
            float4 c1 = *(const float4*)&cS[jj][k0h + 4];
            float cv[8] = {c0.x, c0.y, c0.z, c0.w, c1.x, c1.y, c1.z, c1.w};
            float h1[8];
#pragma unroll
            for (int k = 0; k < 8; k++)
                h1[k] = fmaxf(fmaf(w1g[k], Gv, areg[k]) + cv[k], 0.f);
            // dup-pack h1 -> half2, GEMV: 32 HFMA2 (each lane = full output)
            __half2 h1d[8];
#pragma unroll
            for (int k = 0; k < 8; k++) h1d[k] = __float2half2_rn(h1[k]);
            __half2 t2[4] = {zero2, zero2, zero2, zero2};
#pragma unroll
            for (int op = 0; op < 4; op++)
#pragma unroll
                for (int k = 0; k < 8; k++)
                    t2[op] = __hfma2(W2d[op][k], h1d[k], t2[op]);
            // exchange: send not-owned output pairs, combine owned
            unsigned sA_ = h2u(t2[kh ? 0 : 2]);
            unsigned sB_ = h2u(t2[kh ? 1 : 3]);
            unsigned rA_ = __shfl_xor_sync(0xffffffffu, sA_, 8);
            unsigned rB_ = __shfl_xor_sync(0xffffffffu, sB_, 8);
            __half2 own0 = __hadd2(t2[kh ? 2 : 0], u2h(rA_));
            __half2 own1 = __hadd2(t2[kh ? 3 : 1], u2h(rB_));
            own0 = __hmax2(__hadd2(own0, b2h[0]), zero2);
            own1 = __hmax2(__hadd2(own1, b2h[1]), zero2);
            float2 f0 = __half22float2(own0);
            float2 f1 = __half22float2(own1);
            float mask = (j == i) ? 0.f : 1.f;
            acc[0] = fmaf(mask, f0.x, acc[0]);
            acc[1] = fmaf(mask, f0.y, acc[1]);
            acc[2] = fmaf(mask, f1.x, acc[2]);
            acc[3] = fmaf(mask, f1.y, acc[3]);
        }
    }

#pragma unroll
    for (int o = 0; o < 4; o++) {
        acc[o] += __shfl_down_sync(0xffffffffu, acc[o], 4, 8);
        acc[o] += __shfl_down_sync(0xffffffffu, acc[o], 2, 8);
        acc[o] += __shfl_down_sync(0xffffffffu, acc[o], 1, 8);
    }
    if (jx == 0) {
#pragma unroll
        for (int o = 0; o < 4; o++) s_h2s[iy][kh * 4 + o] = acc[o];
    }
    __syncthreads();

    // ================= GRU epilogue (16 thr per node) =================
    int nl = tid >> 4, t = tid & 15;
    int node = b * Nc + i0 + nl;

    sg[nl][t] = g_g[node * 16 + t];
    if (t < 8) {
        float m = s_bp3[t] * (float)(Nc - 1);
#pragma unroll
        for (int q = 0; q < 8; q++)
            m = fmaf(s_wp3[t * 9 + q], s_h2s[nl][q], m);
        sgin[nl][t] = m;
    } else if (t == 8) {
        sgin[nl][8] = r[node];
    } else if (t == 9) {
        sgin[nl][9] = Sigma[node];
    }
    __syncthreads();

    {
        float ir = s_bih[t],      hr = s_bhh[t];
        float iz = s_bih[16 + t], hz = s_bhh[16 + t];
        float in_ = s_bih[32 + t], hn = s_bhh[32 + t];
#pragma unroll
        for (int k = 0; k < 10; k++) {
            float x = sgin[nl][k];
            ir  = fmaf(s_wih[t * 10 + k],        x, ir);
            iz  = fmaf(s_wih[(16 + t) * 10 + k], x, iz);
            in_ = fmaf(s_wih[(32 + t) * 10 + k], x, in_);
        }
#pragma unroll
        for (int k = 0; k < 16; k++) {
            float x = sg[nl][k];
            hr = fmaf(s_whh[t * 17 + k],        x, hr);
            hz = fmaf(s_whh[(16 + t) * 17 + k], x, hz);
            hn = fmaf(s_whh[(32 + t) * 17 + k], x, hn);
        }
        float rr = sigmoidf_fast(ir + hr);
        float zz = sigmoidf_fast(iz + hz);
        float nn = tanhf_fast(in_ + rr * hn);
        float gv = sg[nl][t];
        float gn = (1.f - zz) * nn + zz * gv;
        sgn[nl][t] = gn;
        g_g[node * 16 + t] = gn;
    }
    __syncthreads();

    if (t < 8) {
        float uv = s_bup[t];
#pragma unroll
        for (int k = 0; k < 16; k++) uv = fmaf(s_wup[t * 17 + k], sgn[nl][k], uv);
        su[nl][t] = uv;
    }
    __syncthreads();

    if (!last) {
        float sig = sigma2[b];
        float av = s_bp1[t] + s_wp1[t * 18 + 17] * sig;
        float cv = 0.f;
#pragma unroll
        for (int k = 0; k < 8; k++) {
            float uv = su[nl][k];
            av = fmaf(s_wp1[t * 18 + k], uv, av);
            cv = fmaf(s_wp1[t * 18 + 8 + k], uv, cv);
        }
        g_ab[wr][node * 16 + t] = av;
        g_cb[wr][node * 16 + t] = cv;
    } else {
        {
            float a = s_br1[t];
#pragma unroll
            for (int k = 0; k < 8; k++) a = fmaf(s_r1[t * 8 + k], su[nl][k], a);
            sh1[nl][t] = fmaxf(a, 0.f);
        }
        __syncthreads();
        if (t < 8) {
            float a = s_br2[t];
#pragma unroll
            for (int k = 0; k < 16; k++) a = fmaf(s_r2[t * 16 + k], sh1[nl][k], a);
            sgin[nl][t] = fmaxf(a, 0.f);
        }
        __syncthreads();
        if (t == 0) {
            float lg[4];
#pragma unroll
            for (int o = 0; o < 4; o++) {
                float a = s_br3[o];
#pragma unroll
                for (int k = 0; k < 8; k++) a = fmaf(s_r3[o * 8 + k], sgin[nl][k], a);
                lg[o] = a;
            }
            float mx = fmaxf(fmaxf(lg[0], lg[1]), fmaxf(lg[2], lg[3]));
            float e0 = __expf(lg[0] - mx), e1 = __expf(lg[1] - mx),
                  e2 = __expf(lg[2] - mx), e3 = __expf(lg[3] - mx);
            float inv = __fdividef(1.f, e0 + e1 + e2 + e3);
            out[node * 4 + 0] = e0 * inv;
            out[node * 4 + 1] = e1 * inv;
            out[node * 4 + 2] = e2 * inv;
            out[node * 4 + 3] = e3 * inv;
        }
        if (t < 8) out[BNc * 4 + node * 8 + t] = su[nl][t];
        out[BNc * 12 + node * 16 + t] = sgn[nl][t];
    }
}

// ============================================================
extern "C" void kernel_launch(void* const* d_in, const int* in_sizes, int n_in,
                              void* d_out, int out_size) {
    const float* y      = (const float*)d_in[0];
    const float* A      = (const float*)d_in[1];
    const float* sigma2 = (const float*)d_in[2];
    const float* r      = (const float*)d_in[3];
    const float* Sigma  = (const float*)d_in[4];
    const float* w_init = (const float*)d_in[5];
    const float* b_init = (const float*)d_in[6];
    const float* w_p1   = (const float*)d_in[7];
    const float* b_p1   = (const float*)d_in[8];
    const float* w_p2   = (const float*)d_in[9];
    const float* b_p2   = (const float*)d_in[10];
    const float* w_p3   = (const float*)d_in[11];
    const float* b_p3   = (const float*)d_in[12];
    const float* w_ih   = (const float*)d_in[13];
    const float* b_ih   = (const float*)d_in[14];
    const float* w_hh   = (const float*)d_in[15];
    const float* b_hh   = (const float*)d_in[16];
    const float* w_up   = (const float*)d_in[17];
    const float* b_up   = (const float*)d_in[18];
    const float* w_r1   = (const float*)d_in[19];
    const float* b_r1   = (const float*)d_in[20];
    const float* w_r2   = (const float*)d_in[21];
    const float* b_r2   = (const float*)d_in[22];
    const float* w_r3   = (const float*)d_in[23];
    const float* b_r3   = (const float*)d_in[24];

    convert_kernel<<<dim3(Nc / 32, Mc / 32, Bc), dim3(32, 8)>>>(A, y);
    gram_mma<<<dim3(36, Bc), 256>>>();
    init_kernel<<<dim3(Nc / 128, Bc), 128>>>(sigma2, w_init, b_init, w_p1, b_p1);
    for (int l = 0; l < 2; l++) {
        pair_fused<<<dim3(Nc / 16, Bc), 256>>>(
            w_p1, b_p1, w_p2, b_p2, w_p3, b_p3, w_ih, b_ih, w_hh, b_hh,
            w_up, b_up, r, Sigma, sigma2,
            w_r1, b_r1, w_r2, b_r2, w_r3, b_r3,
            (float*)d_out, l);
    }
}